// round 17
// baseline (speedup 1.0000x reference)
#include <cuda_runtime.h>
#include <math.h>

// Fixed shapes for EpisodicMemory_57810259804539
#define BB 4
#define HH 16
#define SS 2048
#define DD 64
#define MM 1000
#define KK 10
#define HID (HH*DD)       // 1024
#define TT (SS+KK)        // 2058
#define EPSV 1e-8f

#define N0_4  (BB*SS*HID/4)          // 2,097,152  inputs as float4
#define NQ_4  N0_4                    // q as float4
#define NK_4  (BB*HH*TT*DD/4)         // 2,107,392  k_aug/v_aug as float4
#define HID4  (HID/4)                 // 256 float4 per memory row

#define OUT4_TOTAL  (N0_4 + NQ_4 + 2*NK_4)          // 8,409,088
#define QCOPY_BLOCKS (NQ_4 / 256)                   // 8,192
#define K2_ELEMS4   (N0_4 + 2*NK_4)                 // 6,311,936 (inputs + k/v aug)
#define K2_COPY_BLOCKS (K2_ELEMS4 / 256)            // 24,656

// Scratch
__device__ float g_sims[BB*MM];

// ---------------------------------------------------------------------------
// K1: blocks 0..999     -> sims, one block per memory row m (row loaded once,
//                          dotted against all 4 batch query keys).
//     blocks 1000..9191 -> q pass-through copy (1 float4/thread, proven shape)
//                          filling the ramp window k1 pays anyway.
// ---------------------------------------------------------------------------
__global__ void __launch_bounds__(256) k1_sims_qcopy(
    const float4* __restrict__ k4,
    const float4* __restrict__ mk4,
    const float4* __restrict__ q4,
    float4* __restrict__ out4)
{
    int tid = threadIdx.x;

    if (blockIdx.x >= MM) {
        // q copy: out region starts at N0_4
        int e = (int)(blockIdx.x - MM) * 256 + tid;
        out4[N0_4 + e] = q4[e];
        return;
    }

    int m   = blockIdx.x;
    int wid = tid >> 5, lane = tid & 31;

    float4 r = mk4[m * HID4 + tid];
    float sq = r.x*r.x + r.y*r.y + r.z*r.z + r.w*r.w;

    // query_key[b][i] = k[b, i/64, S-1, i%64]; float4 chunk tid never crosses h
    int h = tid >> 4, d4 = tid & 15;
    float d[BB];
    #pragma unroll
    for (int b = 0; b < BB; b++) {
        float4 qv = k4[((b*HH + h)*SS + (SS-1))*16 + d4];
        d[b] = qv.x*r.x + qv.y*r.y + qv.z*r.z + qv.w*r.w;
    }

    #pragma unroll
    for (int off = 16; off; off >>= 1) {
        sq += __shfl_down_sync(0xffffffffu, sq, off);
        #pragma unroll
        for (int b = 0; b < BB; b++)
            d[b] += __shfl_down_sync(0xffffffffu, d[b], off);
    }

    __shared__ float red[8][5];
    if (lane == 0) {
        red[wid][0] = sq;
        #pragma unroll
        for (int b = 0; b < BB; b++) red[wid][1 + b] = d[b];
    }
    __syncthreads();

    if (tid == 0) {
        float s0 = 0.f, s1 = 0.f, s2 = 0.f, s3 = 0.f, s4 = 0.f;
        #pragma unroll
        for (int w = 0; w < 8; w++) {
            s0 += red[w][0]; s1 += red[w][1]; s2 += red[w][2];
            s3 += red[w][3]; s4 += red[w][4];
        }
        float inv = 1.0f / (sqrtf(s0) + EPSV);
        g_sims[0*MM + m] = s1 * inv;
        g_sims[1*MM + m] = s2 * inv;
        g_sims[2*MM + m] = s3 * inv;
        g_sims[3*MM + m] = s4 * inv;
    }
}

// ---------------------------------------------------------------------------
// K2: blocks 0..3  -> retrieval (proven head placement): top-10, gather t<K
//                    rows, mask_aug, positions_k, scalar.
//     blocks 4..   -> copy of inputs + k_aug/v_aug bodies (q done by K1),
//                    output-major, 1 float4/thread; t<K rows skipped.
// ---------------------------------------------------------------------------
__global__ void __launch_bounds__(256) k2_main(
    const float4* __restrict__ inputs4,
    const float4* __restrict__ k4, const float4* __restrict__ v4,
    const float4* __restrict__ mk4, const float4* __restrict__ mv4,
    const float*  __restrict__ attn_mask,
    const float*  __restrict__ mem_pos,
    float4* __restrict__ out4,
    float*  __restrict__ out,
    int off_mask, int off_pos, int off_seq, int has_scalar)
{
    const int OFFK4 = N0_4 + NQ_4;            // k_aug start (float4)
    const int OFFV4 = OFFK4 + NK_4;           // v_aug start
    int tid = threadIdx.x;

    if (blockIdx.x >= BB) {
        // ---------------- copy blocks (q region excluded) ----------------
        int e = (int)(blockIdx.x - BB) * 256 + tid;   // [0, K2_ELEMS4)
        if (e < N0_4) { out4[e] = inputs4[e]; return; }
        int e2 = e - N0_4;                    // [0, 2*NK_4)
        int which = e2 >= NK_4;
        int e3 = which ? e2 - NK_4 : e2;
        int d4 = e3 & 15;
        int r  = e3 >> 4;                     // bh*TT + t
        int t  = r % TT;
        int bh = r / TT;
        if (t < KK) return;                   // retrieval blocks own these
        const float4* s = which ? v4 : k4;
        out4[e + NQ_4] = s[(bh*SS + (t - KK))*16 + d4];
        return;
    }

    // ---------------- retrieval block for batch b ------------------------
    int b = blockIdx.x;
    __shared__ float ss[MM];
    __shared__ float rv[256];
    __shared__ int   ri[256];
    __shared__ int   top[KK];

    for (int i = tid; i < MM; i += 256)
        ss[i] = g_sims[b*MM + i];
    __syncthreads();

    // top-10: descending, lowest index on ties
    for (int j = 0; j < KK; j++) {
        float bv = -INFINITY; int bi = MM;
        for (int m = tid; m < MM; m += 256) {
            float vv = ss[m];
            if (vv > bv) { bv = vv; bi = m; }   // strict > => lowest idx wins
        }
        rv[tid] = bv; ri[tid] = bi;
        __syncthreads();
        for (int off = 128; off; off >>= 1) {
            if (tid < off) {
                float ov = rv[tid + off]; int oi = ri[tid + off];
                if (ov > rv[tid] || (ov == rv[tid] && oi < ri[tid])) {
                    rv[tid] = ov; ri[tid] = oi;
                }
            }
            __syncthreads();
        }
        if (tid == 0) { top[j] = ri[0]; ss[ri[0]] = -INFINITY; }
        __syncthreads();
    }

    // gather retrieved rows t<K of k_aug / v_aug (5120 float4)
    for (int e = tid; e < 2*KK*HID4; e += 256) {
        int which = e >= KK*HID4;
        int e2 = which ? e - KK*HID4 : e;
        int t  = e2 >> 8;
        int i4 = e2 & 255;
        int idx = top[t];
        float4 val = (which ? mv4 : mk4)[(size_t)idx*HID4 + i4];
        int dst = (which ? OFFV4 : OFFK4)
                + ((b*HH + (i4 >> 4))*TT + t)*16 + (i4 & 15);
        out4[dst] = val;
    }

    // mask_aug[b] = [ones(K), attention_mask[b]]
    for (int t = tid; t < TT; t += 256)
        out[off_mask + b*TT + t] =
            (t < KK) ? 1.0f : attn_mask[b*SS + (t - KK)];

    // positions_k[b] = [arange(S), mem_positions[top_idx[b]]]
    for (int t = tid; t < TT; t += 256)
        out[off_pos + b*TT + t] =
            (t < SS) ? (float)t : mem_pos[top[t - SS]];

    if (b == 0 && tid == 0 && has_scalar)
        out[off_seq] = (float)TT;
}

// ---------------------------------------------------------------------------
extern "C" void kernel_launch(void* const* d_in, const int* in_sizes, int n_in,
                              void* d_out, int out_size)
{
    const float* inputs = (const float*)d_in[0];
    const float* q      = (const float*)d_in[1];
    const float* k      = (const float*)d_in[2];
    const float* v      = (const float*)d_in[3];
    const float* mask   = (const float*)d_in[4];
    const float* mk     = (const float*)d_in[5];
    const float* mv     = (const float*)d_in[6];
    const float* mpos   = (const float*)d_in[7];
    float* out = (float*)d_out;

    const int off_mask = OUT4_TOTAL * 4;                 // after the 4 big tensors
    const int off_tail = off_mask + BB * TT;
    // tuple order: inputs, q, k_aug, v_aug, mask_aug, seq_len_k, positions_k
    const int with_scalar = off_tail + 1 + BB * TT;
    int has_scalar = (out_size == with_scalar) ? 1 : 0;
    const int off_seq = off_tail;
    const int off_pos = off_tail + (has_scalar ? 1 : 0);

    // K1: sims + q copy (fills k1's ramp window with useful bytes)
    k1_sims_qcopy<<<MM + QCOPY_BLOCKS, 256>>>(
        (const float4*)k, (const float4*)mk,
        (const float4*)q, (float4*)out);

    // K2: retrieval + remaining copy (inputs, k_aug, v_aug)
    k2_main<<<BB + K2_COPY_BLOCKS, 256>>>(
        (const float4*)inputs,
        (const float4*)k, (const float4*)v,
        (const float4*)mk, (const float4*)mv,
        mask, mpos,
        (float4*)out, out,
        off_mask, off_pos, off_seq, has_scalar);
}